// round 5
// baseline (speedup 1.0000x reference)
#include <cuda_runtime.h>
#include <cuda_bf16.h>
#include <stdint.h>

#define M_SIZE 4096
#define NMODES 128
#define BATCH  32
#define CH     256
#define NROWS  (BATCH*CH)   // 8192
#define TH     2048         // folded K for fwd

// ---------------- device scratch (allocation-free globals) ----------------
// fwd B tables [m][t] (K-major, t contiguous), hi/lo bf16
__device__ __nv_bfloat16 gBc_h[NMODES*TH], gBc_l[NMODES*TH];   // cos
__device__ __nv_bfloat16 gBs_h[NMODES*TH], gBs_l[NMODES*TH];   // -sin
// inv B tables [m-half][t][64] (m contiguous within half), hi/lo
__device__ __nv_bfloat16 gBic_h[2*TH*64], gBic_l[2*TH*64];     // cos
__device__ __nv_bfloat16 gBis_h[2*TH*64], gBis_l[2*TH*64];     // -sin
// fwd output partials [part][row][m] fp32
__device__ float g_xre[2*NROWS*NMODES], g_xim[2*NROWS*NMODES];
// mix output [m-half][row][64] bf16 hi/lo, scaled
__device__ __nv_bfloat16 g_ore_h[2*NROWS*64], g_ore_l[2*NROWS*64];
__device__ __nv_bfloat16 g_oim_h[2*NROWS*64], g_oim_l[2*NROWS*64];

// ---------------- helpers ----------------
__device__ __forceinline__ uint32_t smem_u32(const void* p) {
    uint32_t a;
    asm("{ .reg .u64 t; cvta.to.shared.u64 t, %1; cvt.u32.u64 %0, t; }" : "=r"(a) : "l"(p));
    return a;
}
#define SW(o) ((uint32_t)(o) ^ ((((uint32_t)(o)) >> 3) & 0x70))

#define CP16(d, s)  asm volatile("cp.async.cg.shared.global [%0], [%1], 16;" :: "r"(d), "l"(s))
#define CP_COMMIT() asm volatile("cp.async.commit_group;")
#define CP_WAIT0()  asm volatile("cp.async.wait_group 0;")

#define LDSM4(R, addr) \
    asm volatile("ldmatrix.sync.aligned.m8n8.x4.shared.b16 {%0,%1,%2,%3}, [%4];" \
        : "=r"((R)[0]), "=r"((R)[1]), "=r"((R)[2]), "=r"((R)[3]) : "r"(addr))

#define MMA4(C, A, b0, b1) \
    asm volatile("mma.sync.aligned.m16n8k16.row.col.f32.bf16.bf16.f32 " \
        "{%0,%1,%2,%3},{%4,%5,%6,%7},{%8,%9},{%0,%1,%2,%3};" \
        : "+f"((C)[0]), "+f"((C)[1]), "+f"((C)[2]), "+f"((C)[3]) \
        : "r"((A)[0]), "r"((A)[1]), "r"((A)[2]), "r"((A)[3]), "r"(b0), "r"(b1))

__device__ __forceinline__ void split_bf16(float v, __nv_bfloat16& h, __nv_bfloat16& l) {
    h = __float2bfloat16(v);
    l = __float2bfloat16(v - __bfloat162float(h));
}
__device__ __forceinline__ float lrelu(float v) { return v >= 0.f ? v : 0.2f * v; }

// smem plane offsets (shared by fwd / inv; per 96KB chunk-buffer)
#define P_A0H 0          // fwd: u_h   | inv: re_h
#define P_A0L 8192
#define P_A1H 16384      // fwd: v_h   | inv: im_h
#define P_A1L 24576
#define P_B0H 32768      // cos_h (16KB plane)
#define P_B0L 49152
#define P_B1H 65536      // -sin_h
#define P_B1L 81920
#define BUFB  98304
#define SMEM_GEMM (2*BUFB)   // 192KB

// ---------------------------------------------------------------------------
// Basis tables
// ---------------------------------------------------------------------------
__global__ void k_basis_fwd() {     // [m][t], t fastest
    int idx = blockIdx.x * blockDim.x + threadIdx.x;   // 128*2048
    int m = idx >> 11, t = idx & (TH - 1);
    int r = (t * m) & (M_SIZE - 1);
    float s, c;
    sincospif((float)r * (1.0f / 2048.0f), &s, &c);
    __nv_bfloat16 h, l;
    split_bf16(c, h, l);  gBc_h[idx] = h; gBc_l[idx] = l;
    split_bf16(-s, h, l); gBs_h[idx] = h; gBs_l[idx] = l;
}
__global__ void k_basis_inv() {     // [half][t][64], m fastest
    int idx = blockIdx.x * blockDim.x + threadIdx.x;   // 2048*128
    int t = idx >> 7, m = idx & 127;
    int r = (t * m) & (M_SIZE - 1);
    float s, c;
    sincospif((float)r * (1.0f / 2048.0f), &s, &c);
    size_t o = ((size_t)(m >> 6) * TH + t) * 64 + (m & 63);
    __nv_bfloat16 h, l;
    split_bf16(c, h, l);  gBic_h[o] = h; gBic_l[o] = l;
    split_bf16(-s, h, l); gBis_h[o] = h; gBis_l[o] = l;
}

// ---------------------------------------------------------------------------
// Forward folded DFT.  Re[m] = sum_t u[t]cos(mtO) (+x[2048](-1)^m),
// Im[m] = sum_t v[t](-sin(mtO)), t=0..2047, u=x[t]+x[4096-t], v=x[t]-x[4096-t].
// CTA: 64 rows x 256 cols (128 re | 128 im), K=1024 per K-split part.
// grid (128 rowblk, 2 part). Warp 32r x 64c.
// ---------------------------------------------------------------------------
__global__ void __launch_bounds__(256, 1) k_fwd(const float* __restrict__ x) {
    extern __shared__ char sm[];
    uint32_t sb = smem_u32(sm);
    const int tid = threadIdx.x, lane = tid & 31, wid = tid >> 5;
    const int wm = wid & 1, wn = wid >> 1;          // wn 0..3
    const int row0 = blockIdx.x * 64;
    const int part = blockIdx.y;
    const bool is_re = (wn < 2);

    uint32_t offA[2], offB[4];
#pragma unroll
    for (int mf = 0; mf < 2; mf++)
        offA[mf] = (wm*32 + mf*16 + (lane & 15)) * 128 + (lane >> 4) * 16;
#pragma unroll
    for (int p = 0; p < 4; p++)
        offB[p] = ((wn & 1)*64 + p*16 + ((lane >> 4) << 3) + (lane & 7)) * 128
                + ((lane >> 3) & 1) * 16;

    float acc[2][8][4];
#pragma unroll
    for (int i = 0; i < 2; i++)
#pragma unroll
        for (int j = 0; j < 8; j++)
#pragma unroll
            for (int q = 0; q < 4; q++) acc[i][j][q] = 0.0f;

    // A loader lambda-ish: per chunk, 64 rows x 64 t (16 float4 groups); 4 iters.
    // B loader: 4 planes x 128 m-rows x 8 cb.
    const int NCHUNK = 16;   // 1024 / 64

    // ---- preload chunk 0 ----
    {
        const int t0 = part * 1024;
#pragma unroll
        for (int p = 0; p < 4; p++) {
            const __nv_bfloat16* s = (p == 0) ? gBc_h : (p == 1) ? gBc_l
                                   : (p == 2) ? gBs_h : gBs_l;
            const uint32_t dpl = sb + P_B0H + p * 16384;
#pragma unroll
            for (int j = 0; j < 4; j++) {
                int f = tid + j * 256;               // 1024 = 128 x 8
                int r = f >> 3, cb = f & 7;
                CP16(dpl + SW(r * 128 + cb * 16), s + (size_t)r * TH + t0 + cb * 8);
            }
        }
        CP_COMMIT();
#pragma unroll
        for (int it = 0; it < 4; it++) {
            int f = tid + it * 256;
            int r = f >> 4, q = f & 15;
            int gt = t0 + q * 4;
            size_t rb = (size_t)(row0 + r) * M_SIZE;
            float4 xv = *(const float4*)&x[rb + gt];
            float xm0 = (gt == 0) ? 0.f : x[rb + M_SIZE - gt];
            float xm1 = x[rb + M_SIZE - gt - 1];
            float xm2 = x[rb + M_SIZE - gt - 2];
            float xm3 = x[rb + M_SIZE - gt - 3];
            float u0 = xv.x + xm0, u1 = xv.y + xm1, u2 = xv.z + xm2, u3 = xv.w + xm3;
            float v0 = xv.x - xm0, v1 = xv.y - xm1, v2 = xv.z - xm2, v3 = xv.w - xm3;
            __nv_bfloat16 h0,l0,h1,l1,h2,l2,h3,l3;
            uint32_t off = SW(r * 128 + q * 8);
            split_bf16(u0,h0,l0); split_bf16(u1,h1,l1); split_bf16(u2,h2,l2); split_bf16(u3,h3,l3);
            { __nv_bfloat162 a = __halves2bfloat162(h0,h1), b = __halves2bfloat162(h2,h3);
              *(uint2*)(sm + P_A0H + off) = make_uint2(*(uint32_t*)&a, *(uint32_t*)&b); }
            { __nv_bfloat162 a = __halves2bfloat162(l0,l1), b = __halves2bfloat162(l2,l3);
              *(uint2*)(sm + P_A0L + off) = make_uint2(*(uint32_t*)&a, *(uint32_t*)&b); }
            split_bf16(v0,h0,l0); split_bf16(v1,h1,l1); split_bf16(v2,h2,l2); split_bf16(v3,h3,l3);
            { __nv_bfloat162 a = __halves2bfloat162(h0,h1), b = __halves2bfloat162(h2,h3);
              *(uint2*)(sm + P_A1H + off) = make_uint2(*(uint32_t*)&a, *(uint32_t*)&b); }
            { __nv_bfloat162 a = __halves2bfloat162(l0,l1), b = __halves2bfloat162(l2,l3);
              *(uint2*)(sm + P_A1L + off) = make_uint2(*(uint32_t*)&a, *(uint32_t*)&b); }
        }
        CP_WAIT0();
    }
    __syncthreads();

    for (int cc = 0; cc < NCHUNK; cc++) {
        uint32_t bb = sb + (cc & 1) * BUFB;
        char*    nbp = sm + ((cc + 1) & 1) * BUFB;
        uint32_t nbb = sb + ((cc + 1) & 1) * BUFB;
        bool pf = (cc + 1 < NCHUNK);
        float4 va[4]; float vm[4][4]; int rr[4], qq[4];
        if (pf) {
            const int t1 = part * 1024 + (cc + 1) * 64;
#pragma unroll
            for (int p = 0; p < 4; p++) {
                const __nv_bfloat16* s = (p == 0) ? gBc_h : (p == 1) ? gBc_l
                                       : (p == 2) ? gBs_h : gBs_l;
                const uint32_t dpl = nbb + P_B0H + p * 16384;
#pragma unroll
                for (int j = 0; j < 4; j++) {
                    int f = tid + j * 256;
                    int r = f >> 3, cb = f & 7;
                    CP16(dpl + SW(r * 128 + cb * 16), s + (size_t)r * TH + t1 + cb * 8);
                }
            }
            CP_COMMIT();
#pragma unroll
            for (int it = 0; it < 4; it++) {
                int f = tid + it * 256;
                rr[it] = f >> 4; qq[it] = f & 15;
                int gt = t1 + qq[it] * 4;
                size_t rb = (size_t)(row0 + rr[it]) * M_SIZE;
                va[it] = *(const float4*)&x[rb + gt];
                vm[it][0] = x[rb + M_SIZE - gt];       // gt>=64 here, never 0
                vm[it][1] = x[rb + M_SIZE - gt - 1];
                vm[it][2] = x[rb + M_SIZE - gt - 2];
                vm[it][3] = x[rb + M_SIZE - gt - 3];
            }
        }
        // ---- MMA: 4 k16 steps, 3 split products ----
        const uint32_t Ah = bb + (is_re ? P_A0H : P_A1H);
        const uint32_t Al = Ah + 8192;
        const uint32_t Bh = bb + (is_re ? P_B0H : P_B1H);
        const uint32_t Bl = Bh + 16384;
#pragma unroll
        for (int ks = 0; ks < 4; ks++) {
            uint32_t Af[2][4], Bf[4][4], Bo[4][4];
#pragma unroll
            for (int mf = 0; mf < 2; mf++) LDSM4(Af[mf], Ah + SW(offA[mf] + ks * 32));
#pragma unroll
            for (int p = 0; p < 4; p++)    LDSM4(Bf[p],  Bh + SW(offB[p] + ks * 32));
#pragma unroll
            for (int mf = 0; mf < 2; mf++)
#pragma unroll
                for (int nf = 0; nf < 8; nf++)
                    MMA4(acc[mf][nf], Af[mf], Bf[nf>>1][(nf&1)*2], Bf[nf>>1][(nf&1)*2+1]);
#pragma unroll
            for (int p = 0; p < 4; p++)    LDSM4(Bo[p],  Bl + SW(offB[p] + ks * 32));
#pragma unroll
            for (int mf = 0; mf < 2; mf++)
#pragma unroll
                for (int nf = 0; nf < 8; nf++)
                    MMA4(acc[mf][nf], Af[mf], Bo[nf>>1][(nf&1)*2], Bo[nf>>1][(nf&1)*2+1]);
#pragma unroll
            for (int mf = 0; mf < 2; mf++) LDSM4(Af[mf], Al + SW(offA[mf] + ks * 32));
#pragma unroll
            for (int mf = 0; mf < 2; mf++)
#pragma unroll
                for (int nf = 0; nf < 8; nf++)
                    MMA4(acc[mf][nf], Af[mf], Bf[nf>>1][(nf&1)*2], Bf[nf>>1][(nf&1)*2+1]);
        }
        if (pf) {
#pragma unroll
            for (int it = 0; it < 4; it++) {
                float4 xv = va[it];
                float u0 = xv.x + vm[it][0], u1 = xv.y + vm[it][1],
                      u2 = xv.z + vm[it][2], u3 = xv.w + vm[it][3];
                float v0 = xv.x - vm[it][0], v1 = xv.y - vm[it][1],
                      v2 = xv.z - vm[it][2], v3 = xv.w - vm[it][3];
                __nv_bfloat16 h0,l0,h1,l1,h2,l2,h3,l3;
                uint32_t off = SW(rr[it] * 128 + qq[it] * 8);
                split_bf16(u0,h0,l0); split_bf16(u1,h1,l1); split_bf16(u2,h2,l2); split_bf16(u3,h3,l3);
                { __nv_bfloat162 a = __halves2bfloat162(h0,h1), b = __halves2bfloat162(h2,h3);
                  *(uint2*)(nbp + P_A0H + off) = make_uint2(*(uint32_t*)&a, *(uint32_t*)&b); }
                { __nv_bfloat162 a = __halves2bfloat162(l0,l1), b = __halves2bfloat162(l2,l3);
                  *(uint2*)(nbp + P_A0L + off) = make_uint2(*(uint32_t*)&a, *(uint32_t*)&b); }
                split_bf16(v0,h0,l0); split_bf16(v1,h1,l1); split_bf16(v2,h2,l2); split_bf16(v3,h3,l3);
                { __nv_bfloat162 a = __halves2bfloat162(h0,h1), b = __halves2bfloat162(h2,h3);
                  *(uint2*)(nbp + P_A1H + off) = make_uint2(*(uint32_t*)&a, *(uint32_t*)&b); }
                { __nv_bfloat162 a = __halves2bfloat162(l0,l1), b = __halves2bfloat162(l2,l3);
                  *(uint2*)(nbp + P_A1L + off) = make_uint2(*(uint32_t*)&a, *(uint32_t*)&b); }
            }
        }
        CP_WAIT0();
        __syncthreads();
    }

    // ---- epilogue: write partials; part 0 re-warps add x[2048](-1)^m ----
    float* plane = (is_re ? g_xre : g_xim) + (size_t)part * NROWS * NMODES;
#pragma unroll
    for (int mf = 0; mf < 2; mf++) {
        int r  = row0 + wm*32 + mf*16 + (lane >> 2);
        float c0 = 0.f, c1 = 0.f;
        if (is_re && part == 0) {
            c0 = x[(size_t)r * M_SIZE + 2048];
            c1 = x[(size_t)(r + 8) * M_SIZE + 2048];
        }
#pragma unroll
        for (int nf = 0; nf < 8; nf++) {
            int col = (wn & 1)*64 + nf*8 + (lane & 3)*2;   // even
            float v0 = acc[mf][nf][0] + c0, v1 = acc[mf][nf][1] - c0;
            float v2 = acc[mf][nf][2] + c1, v3 = acc[mf][nf][3] - c1;
            *(float2*)&plane[(size_t)r * NMODES + col]       = make_float2(v0, v1);
            *(float2*)&plane[(size_t)(r + 8) * NMODES + col] = make_float2(v2, v3);
        }
    }
}

// ---------------------------------------------------------------------------
// Mode mixing (SIMT). grid (32 o-blk, 4 m-grp, 2 b-grp), 256 thr.
// Sums the two fwd K-partials during the smem load. Output scaled bf16 planes.
// ---------------------------------------------------------------------------
#define MIXB 16
__global__ void __launch_bounds__(256) k_mix(const float2* __restrict__ w2) {
    __shared__ float2 Xs[8 * MIXB * 32];   // 32KB
    const int tid = threadIdx.x, lane = tid & 31, wid = tid >> 5;
    const int o  = blockIdx.x * 8 + wid;
    const int m0 = blockIdx.y * 32;
    const int b0 = blockIdx.z * MIXB;
    const int m  = m0 + lane;

    float ar[MIXB], ai[MIXB];
#pragma unroll
    for (int b = 0; b < MIXB; b++) { ar[b] = 0.f; ai[b] = 0.f; }

    for (int it = 0; it < 32; it++) {
        const int i0 = it * 8;
        __syncthreads();
#pragma unroll
        for (int j = 0; j < 16; j++) {
            int f = tid + j * 256;
            int ii = f >> 9, b = (f >> 5) & (MIXB - 1), ml = f & 31;
            size_t idx = (size_t)((b0 + b) * CH + i0 + ii) * NMODES + m0 + ml;
            float re = g_xre[idx] + g_xre[(size_t)NROWS * NMODES + idx];
            float im = g_xim[idx] + g_xim[(size_t)NROWS * NMODES + idx];
            Xs[f] = make_float2(re, im);
        }
        __syncthreads();
#pragma unroll
        for (int ii = 0; ii < 8; ii++) {
            float2 w = w2[((size_t)o * CH + i0 + ii) * NMODES + m];
            const float2* xr = &Xs[ii * (MIXB * 32) + lane];
#pragma unroll
            for (int b = 0; b < MIXB; b++) {
                float2 xv = xr[b * 32];
                ar[b] += xv.x * w.x - xv.y * w.y;
                ai[b] += xv.x * w.y + xv.y * w.x;
            }
        }
    }
    const float sc = (m == 0 ? 1.0f : 2.0f) * (1.0f / (float)M_SIZE);
    const int half = m >> 6, ml = m & 63;
#pragma unroll
    for (int b = 0; b < MIXB; b++) {
        int row = (b0 + b) * CH + o;
        size_t i = ((size_t)half * NROWS + row) * 64 + ml;
        __nv_bfloat16 h, l;
        split_bf16(ar[b] * sc, h, l); g_ore_h[i] = h; g_ore_l[i] = l;
        split_bf16(ai[b] * sc, h, l); g_oim_h[i] = h; g_oim_l[i] = l;
    }
}

// ---------------------------------------------------------------------------
// Inverse folded DFT + butterfly + LeakyReLU + residual.
// P[t]=sum c_re cos, Q[t]=sum c_im(-sin); out[t]=x+lrelu(P+Q), out[4096-t]=x+lrelu(P-Q).
// CTA: 64 rows x 128 t (256 out cols: P|Q), K=128 (2 chunks of 64, loaded upfront).
// grid (16 tblk, 128 rowblk).
// ---------------------------------------------------------------------------
__global__ void __launch_bounds__(256, 1) k_inv(const float* __restrict__ x,
                                                float* __restrict__ out) {
    extern __shared__ char sm[];
    uint32_t sb = smem_u32(sm);
    const int tid = threadIdx.x, lane = tid & 31, wid = tid >> 5;
    const int wm = wid & 1, wn = wid >> 1;
    const int t0   = blockIdx.x * 128;
    const int row0 = blockIdx.y * 64;
    const bool is_p = (wn < 2);

    uint32_t offA[2], offB[4];
#pragma unroll
    for (int mf = 0; mf < 2; mf++)
        offA[mf] = (wm*32 + mf*16 + (lane & 15)) * 128 + (lane >> 4) * 16;
#pragma unroll
    for (int p = 0; p < 4; p++)
        offB[p] = ((wn & 1)*64 + p*16 + ((lane >> 4) << 3) + (lane & 7)) * 128
                + ((lane >> 3) & 1) * 16;

    // ---- load all K=128 (2 chunks) via cp.async ----
#pragma unroll
    for (int p = 0; p < 4; p++) {
        const __nv_bfloat16* s = (p == 0) ? g_ore_h : (p == 1) ? g_ore_l
                               : (p == 2) ? g_oim_h : g_oim_l;
#pragma unroll
        for (int c = 0; c < 2; c++) {
#pragma unroll
            for (int j = 0; j < 2; j++) {
                int f = tid + j * 256;               // 512 = 64 x 8
                int r = f >> 3, cb = f & 7;
                CP16(sb + c*BUFB + P_A0H + p*8192 + SW(r * 128 + cb * 16),
                     s + ((size_t)c * NROWS + row0 + r) * 64 + cb * 8);
            }
        }
    }
#pragma unroll
    for (int p = 0; p < 4; p++) {
        const __nv_bfloat16* s = (p == 0) ? gBic_h : (p == 1) ? gBic_l
                               : (p == 2) ? gBis_h : gBis_l;
#pragma unroll
        for (int c = 0; c < 2; c++) {
#pragma unroll
            for (int j = 0; j < 4; j++) {
                int f = tid + j * 256;               // 1024 = 128 x 8
                int t = f >> 3, cb = f & 7;
                CP16(sb + c*BUFB + P_B0H + p*16384 + SW(t * 128 + cb * 16),
                     s + ((size_t)c * TH + t0 + t) * 64 + cb * 8);
            }
        }
    }
    CP_COMMIT();

    float acc[2][8][4];
#pragma unroll
    for (int i = 0; i < 2; i++)
#pragma unroll
        for (int j = 0; j < 8; j++)
#pragma unroll
            for (int q = 0; q < 4; q++) acc[i][j][q] = 0.0f;

    CP_WAIT0();
    __syncthreads();

#pragma unroll
    for (int c = 0; c < 2; c++) {
        const uint32_t cb0 = sb + c * BUFB;
        const uint32_t Ah = cb0 + (is_p ? P_A0H : P_A1H);
        const uint32_t Al = Ah + 8192;
        const uint32_t Bh = cb0 + (is_p ? P_B0H : P_B1H);
        const uint32_t Bl = Bh + 16384;
#pragma unroll
        for (int ks = 0; ks < 4; ks++) {
            uint32_t Af[2][4], Bf[4][4], Bo[4][4];
#pragma unroll
            for (int mf = 0; mf < 2; mf++) LDSM4(Af[mf], Ah + SW(offA[mf] + ks * 32));
#pragma unroll
            for (int p = 0; p < 4; p++)    LDSM4(Bf[p],  Bh + SW(offB[p] + ks * 32));
#pragma unroll
            for (int mf = 0; mf < 2; mf++)
#pragma unroll
                for (int nf = 0; nf < 8; nf++)
                    MMA4(acc[mf][nf], Af[mf], Bf[nf>>1][(nf&1)*2], Bf[nf>>1][(nf&1)*2+1]);
#pragma unroll
            for (int p = 0; p < 4; p++)    LDSM4(Bo[p],  Bl + SW(offB[p] + ks * 32));
#pragma unroll
            for (int mf = 0; mf < 2; mf++)
#pragma unroll
                for (int nf = 0; nf < 8; nf++)
                    MMA4(acc[mf][nf], Af[mf], Bo[nf>>1][(nf&1)*2], Bo[nf>>1][(nf&1)*2+1]);
#pragma unroll
            for (int mf = 0; mf < 2; mf++) LDSM4(Af[mf], Al + SW(offA[mf] + ks * 32));
#pragma unroll
            for (int mf = 0; mf < 2; mf++)
#pragma unroll
                for (int nf = 0; nf < 8; nf++)
                    MMA4(acc[mf][nf], Af[mf], Bf[nf>>1][(nf&1)*2], Bf[nf>>1][(nf&1)*2+1]);
        }
    }

    // ---- butterfly epilogue through smem ----
    __syncthreads();
    float (*sPQ)[258] = (float(*)[258])sm;   // 64 x 258 floats (padded)
#pragma unroll
    for (int mf = 0; mf < 2; mf++) {
        int r = wm*32 + mf*16 + (lane >> 2);
#pragma unroll
        for (int nf = 0; nf < 8; nf++) {
            int col = wn*64 + nf*8 + (lane & 3)*2;
            sPQ[r][col]     = acc[mf][nf][0];
            sPQ[r][col + 1] = acc[mf][nf][1];
            sPQ[r + 8][col]     = acc[mf][nf][2];
            sPQ[r + 8][col + 1] = acc[mf][nf][3];
        }
    }
    __syncthreads();
    for (int f = tid; f < 64 * 128; f += 256) {
        int r = f >> 7, tl = f & 127;
        float P = sPQ[r][tl], Q = sPQ[r][tl + 128];
        int row = row0 + r, t = t0 + tl;
        size_t bidx = (size_t)row * M_SIZE + t;
        out[bidx] = x[bidx] + lrelu(P + Q);
        if (t) {
            size_t midx = (size_t)row * M_SIZE + M_SIZE - t;
            out[midx] = x[midx] + lrelu(P - Q);
        }
    }
}

// ---------------------------------------------------------------------------
// t = 2048 column: out[row][2048] = x + lrelu( sum_m c_re[m] * (-1)^m )
// ---------------------------------------------------------------------------
__global__ void k_t2048(const float* __restrict__ x, float* __restrict__ out) {
    int row = blockIdx.x * blockDim.x + threadIdx.x;
    float sum = 0.f;
#pragma unroll 4
    for (int m = 0; m < NMODES; m++) {
        size_t i = ((size_t)(m >> 6) * NROWS + row) * 64 + (m & 63);
        float cre = __bfloat162float(g_ore_h[i]) + __bfloat162float(g_ore_l[i]);
        sum += (m & 1) ? -cre : cre;
    }
    size_t idx = (size_t)row * M_SIZE + 2048;
    out[idx] = x[idx] + lrelu(sum);
}

// ---------------------------------------------------------------------------
extern "C" void kernel_launch(void* const* d_in, const int* in_sizes, int n_in,
                              void* d_out, int out_size) {
    (void)in_sizes; (void)n_in; (void)out_size;
    const float*  x  = (const float*)d_in[0];
    const float2* w2 = (const float2*)d_in[1];
    float* out = (float*)d_out;

    cudaFuncSetAttribute(k_fwd, cudaFuncAttributeMaxDynamicSharedMemorySize, SMEM_GEMM);
    cudaFuncSetAttribute(k_inv, cudaFuncAttributeMaxDynamicSharedMemorySize, SMEM_GEMM);

    k_basis_fwd<<<(NMODES * TH) / 256, 256>>>();
    k_basis_inv<<<(TH * NMODES) / 256, 256>>>();
    k_fwd<<<dim3(NROWS / 64, 2), 256, SMEM_GEMM>>>(x);
    k_mix<<<dim3(CH / 8, NMODES / 32, BATCH / MIXB), 256>>>(w2);
    k_inv<<<dim3(TH / 128, NROWS / 64), 256, SMEM_GEMM>>>(x, out);
    k_t2048<<<NROWS / 256, 256>>>(x, out);
}

// round 6
// speedup vs baseline: 1.4102x; 1.4102x over previous
#include <cuda_runtime.h>
#include <cuda_bf16.h>
#include <stdint.h>

#define M_SIZE 4096
#define NMODES 128
#define BATCH  32
#define CH     256
#define NROWS  (BATCH*CH)   // 8192
#define NC     (2*NMODES)   // 256

// ---------------- device scratch (allocation-free globals) ----------------
__device__ __nv_bfloat16 g_basis_h[(size_t)M_SIZE*NC];   // [t][c]  (inv B)
__device__ __nv_bfloat16 g_basis_l[(size_t)M_SIZE*NC];
__device__ __nv_bfloat16 g_basisT_h[(size_t)NC*M_SIZE];  // [c][t]  (fwd B)
__device__ __nv_bfloat16 g_basisT_l[(size_t)NC*M_SIZE];
__device__ float         g_xftT[(size_t)NC*NROWS];       // [c][row] fp32
// weight planes [m][o][i] bf16 hi/lo
__device__ __nv_bfloat16 gWre_h[(size_t)NMODES*CH*CH], gWre_l[(size_t)NMODES*CH*CH];
__device__ __nv_bfloat16 gWim_h[(size_t)NMODES*CH*CH], gWim_l[(size_t)NMODES*CH*CH];
__device__ __nv_bfloat16 g_oft_h[(size_t)NROWS*NC];      // [row][c] scaled
__device__ __nv_bfloat16 g_oft_l[(size_t)NROWS*NC];

// ---------------- helpers ----------------
__device__ __forceinline__ uint32_t smem_u32(const void* p) {
    uint32_t a;
    asm("{ .reg .u64 t; cvta.to.shared.u64 t, %1; cvt.u32.u64 %0, t; }" : "=r"(a) : "l"(p));
    return a;
}
#define SW(o) ((uint32_t)(o) ^ ((((uint32_t)(o)) >> 3) & 0x70))

#define CP16(d, s)  asm volatile("cp.async.cg.shared.global [%0], [%1], 16;" :: "r"(d), "l"(s))
#define CP_COMMIT() asm volatile("cp.async.commit_group;")
#define CP_WAIT0()  asm volatile("cp.async.wait_group 0;")

#define LDSM4(R, addr) \
    asm volatile("ldmatrix.sync.aligned.m8n8.x4.shared.b16 {%0,%1,%2,%3}, [%4];" \
        : "=r"((R)[0]), "=r"((R)[1]), "=r"((R)[2]), "=r"((R)[3]) : "r"(addr))

#define MMA4(C, A, b0, b1) \
    asm volatile("mma.sync.aligned.m16n8k16.row.col.f32.bf16.bf16.f32 " \
        "{%0,%1,%2,%3},{%4,%5,%6,%7},{%8,%9},{%0,%1,%2,%3};" \
        : "+f"((C)[0]), "+f"((C)[1]), "+f"((C)[2]), "+f"((C)[3]) \
        : "r"((A)[0]), "r"((A)[1]), "r"((A)[2]), "r"((A)[3]), "r"(b0), "r"(b1))

__device__ __forceinline__ void split_bf16(float v, __nv_bfloat16& h, __nv_bfloat16& l) {
    h = __float2bfloat16(v);
    l = __float2bfloat16(v - __bfloat162float(h));
}
__device__ __forceinline__ uint2 pack4(__nv_bfloat16 a, __nv_bfloat16 b,
                                       __nv_bfloat16 c, __nv_bfloat16 d) {
    __nv_bfloat162 p = __halves2bfloat162(a, b), q = __halves2bfloat162(c, d);
    return make_uint2(*(uint32_t*)&p, *(uint32_t*)&q);
}

// smem plane offsets for fwd/inv (per 64KB buffer)
#define P_AH 0
#define P_AL 16384
#define P_BH 32768
#define P_BL 49152
#define BUFB 65536
#define SMEM_GEMM (2*BUFB)

// ---------------------------------------------------------------------------
// Basis tables
// ---------------------------------------------------------------------------
__global__ void k_basis_a() {   // [t][c]
    int idx = blockIdx.x * blockDim.x + threadIdx.x;
    int t = idx >> 7, m = idx & 127;
    int r = (t * m) & (M_SIZE - 1);
    float s, c;
    sincospif((float)r * (1.0f / 2048.0f), &s, &c);
    __nv_bfloat16 ch, cl, sh, sl;
    split_bf16(c, ch, cl); split_bf16(-s, sh, sl);
    size_t b = (size_t)t * NC + 2 * m;
    *(__nv_bfloat162*)&g_basis_h[b] = __halves2bfloat162(ch, sh);
    *(__nv_bfloat162*)&g_basis_l[b] = __halves2bfloat162(cl, sl);
}
__global__ void k_basis_b() {   // [c][t]
    int idx = blockIdx.x * blockDim.x + threadIdx.x;
    int m = idx >> 12, t = idx & 4095;
    int r = (t * m) & (M_SIZE - 1);
    float s, c;
    sincospif((float)r * (1.0f / 2048.0f), &s, &c);
    __nv_bfloat16 ch, cl, sh, sl;
    split_bf16(c, ch, cl); split_bf16(-s, sh, sl);
    g_basisT_h[(size_t)(2*m)   * M_SIZE + t] = ch;
    g_basisT_h[(size_t)(2*m+1) * M_SIZE + t] = sh;
    g_basisT_l[(size_t)(2*m)   * M_SIZE + t] = cl;
    g_basisT_l[(size_t)(2*m+1) * M_SIZE + t] = sl;
}

// ---------------------------------------------------------------------------
// Weight transpose: w2[o][i][m] float2 -> planes [m][o][i] bf16 hi/lo.
// Grid (4 i-blk, 4 m-blk, 256 o), 256 threads.
// ---------------------------------------------------------------------------
__global__ void __launch_bounds__(256) k_wtransp(const float2* __restrict__ w2) {
    __shared__ float2 s[64][33];
    const int o  = blockIdx.z;
    const int i0 = blockIdx.x * 64;
    const int m0 = blockIdx.y * 32;
    const int tid = threadIdx.x;
#pragma unroll
    for (int j = 0; j < 8; j++) {
        int f = tid + j * 256;
        int ii = f >> 5, ml = f & 31;
        s[ii][ml] = w2[((size_t)o * CH + i0 + ii) * NMODES + m0 + ml];
    }
    __syncthreads();
#pragma unroll
    for (int j = 0; j < 2; j++) {
        int f = tid + j * 256;
        int ml = f >> 4, ig = (f & 15) * 4;
        float2 v0 = s[ig][ml], v1 = s[ig+1][ml], v2 = s[ig+2][ml], v3 = s[ig+3][ml];
        size_t dst = ((size_t)(m0 + ml) * CH + o) * CH + i0 + ig;
        __nv_bfloat16 h0,l0,h1,l1,h2,l2,h3,l3;
        split_bf16(v0.x,h0,l0); split_bf16(v1.x,h1,l1);
        split_bf16(v2.x,h2,l2); split_bf16(v3.x,h3,l3);
        *(uint2*)&gWre_h[dst] = pack4(h0,h1,h2,h3);
        *(uint2*)&gWre_l[dst] = pack4(l0,l1,l2,l3);
        split_bf16(v0.y,h0,l0); split_bf16(v1.y,h1,l1);
        split_bf16(v2.y,h2,l2); split_bf16(v3.y,h3,l3);
        *(uint2*)&gWim_h[dst] = pack4(h0,h1,h2,h3);
        *(uint2*)&gWim_l[dst] = pack4(l0,l1,l2,l3);
    }
}

// ---------------------------------------------------------------------------
// Forward DFT: xftT[c][row] = sum_k x[row][k] * basisT[c][k]
// mma.sync bf16 split (hh+hl+lh). Block 128x128, 8 warps (64x32), K-chunk 64.
// ---------------------------------------------------------------------------
__global__ void __launch_bounds__(256, 1) k_fwd(const float* __restrict__ x) {
    extern __shared__ char sm[];
    uint32_t sb = smem_u32(sm);
    const int tid = threadIdx.x, lane = tid & 31, wid = tid >> 5;
    const int wm = wid & 1, wn = wid >> 1;
    const int row0 = blockIdx.x * 128;
    const int c0   = blockIdx.y * 128;

    uint32_t offA[4], offB[2];
#pragma unroll
    for (int mf = 0; mf < 4; mf++)
        offA[mf] = (wm*64 + mf*16 + (lane & 15)) * 128 + (lane >> 4) * 16;
#pragma unroll
    for (int p = 0; p < 2; p++)
        offB[p] = (wn*32 + p*16 + ((lane >> 4) << 3) + (lane & 7)) * 128
                + ((lane >> 3) & 1) * 16;

    float acc[4][4][4];
#pragma unroll
    for (int i = 0; i < 4; i++)
#pragma unroll
        for (int j = 0; j < 4; j++)
#pragma unroll
            for (int q = 0; q < 4; q++) acc[i][j][q] = 0.0f;

    // ---- preload chunk 0 ----
    {
        const int k0 = 0;
#pragma unroll
        for (int j = 0; j < 8; j++) {
            int f = tid + j * 256;
            int plane = f >> 10, r = (f >> 3) & 127, cb = f & 7;
            const __nv_bfloat16* src = (plane ? g_basisT_l : g_basisT_h)
                                     + (size_t)(c0 + r) * M_SIZE + k0 + cb * 8;
            CP16(sb + P_BH + plane * 16384 + SW(r * 128 + cb * 16), src);
        }
        CP_COMMIT();
#pragma unroll
        for (int it = 0; it < 8; it++) {
            int f = tid + it * 256;
            int r = f >> 4, q = f & 15;
            float4 v = *(const float4*)&x[(size_t)(row0 + r) * M_SIZE + k0 + q * 4];
            __nv_bfloat16 h0,l0,h1,l1,h2,l2,h3,l3;
            split_bf16(v.x,h0,l0); split_bf16(v.y,h1,l1);
            split_bf16(v.z,h2,l2); split_bf16(v.w,h3,l3);
            uint32_t off = SW(r * 128 + q * 8);
            *(uint2*)(sm + P_AH + off) = pack4(h0,h1,h2,h3);
            *(uint2*)(sm + P_AL + off) = pack4(l0,l1,l2,l3);
        }
        CP_WAIT0();
    }
    __syncthreads();

    const int NCHUNK = M_SIZE / 64;
    for (int cc = 0; cc < NCHUNK; cc++) {
        uint32_t bb = sb + (cc & 1) * BUFB;
        char*    nbp = sm + ((cc + 1) & 1) * BUFB;
        uint32_t nbb = sb + ((cc + 1) & 1) * BUFB;
        bool pf = (cc + 1 < NCHUNK);
        float4 va[8];
        int rpf[8], qpf[8];
        if (pf) {
            const int k1 = (cc + 1) * 64;
#pragma unroll
            for (int j = 0; j < 8; j++) {
                int f = tid + j * 256;
                int plane = f >> 10, r = (f >> 3) & 127, cb = f & 7;
                const __nv_bfloat16* src = (plane ? g_basisT_l : g_basisT_h)
                                         + (size_t)(c0 + r) * M_SIZE + k1 + cb * 8;
                CP16(nbb + P_BH + plane * 16384 + SW(r * 128 + cb * 16), src);
            }
            CP_COMMIT();
#pragma unroll
            for (int it = 0; it < 8; it++) {
                int f = tid + it * 256;
                rpf[it] = f >> 4; qpf[it] = f & 15;
                va[it] = *(const float4*)&x[(size_t)(row0 + rpf[it]) * M_SIZE + k1 + qpf[it] * 4];
            }
        }
#pragma unroll
        for (int ks = 0; ks < 4; ks++) {
            uint32_t Af[4][4], Bh[2][4], Bo[2][4];
#pragma unroll
            for (int mf = 0; mf < 4; mf++) LDSM4(Af[mf], bb + P_AH + SW(offA[mf] + ks * 32));
#pragma unroll
            for (int p = 0; p < 2; p++)    LDSM4(Bh[p],  bb + P_BH + SW(offB[p] + ks * 32));
#pragma unroll
            for (int mf = 0; mf < 4; mf++)
#pragma unroll
                for (int nf = 0; nf < 4; nf++)
                    MMA4(acc[mf][nf], Af[mf], Bh[nf>>1][(nf&1)*2], Bh[nf>>1][(nf&1)*2+1]);
#pragma unroll
            for (int p = 0; p < 2; p++)    LDSM4(Bo[p],  bb + P_BL + SW(offB[p] + ks * 32));
#pragma unroll
            for (int mf = 0; mf < 4; mf++)
#pragma unroll
                for (int nf = 0; nf < 4; nf++)
                    MMA4(acc[mf][nf], Af[mf], Bo[nf>>1][(nf&1)*2], Bo[nf>>1][(nf&1)*2+1]);
#pragma unroll
            for (int mf = 0; mf < 4; mf++) LDSM4(Af[mf], bb + P_AL + SW(offA[mf] + ks * 32));
#pragma unroll
            for (int mf = 0; mf < 4; mf++)
#pragma unroll
                for (int nf = 0; nf < 4; nf++)
                    MMA4(acc[mf][nf], Af[mf], Bh[nf>>1][(nf&1)*2], Bh[nf>>1][(nf&1)*2+1]);
        }
        if (pf) {
#pragma unroll
            for (int it = 0; it < 8; it++) {
                float4 v = va[it];
                __nv_bfloat16 h0,l0,h1,l1,h2,l2,h3,l3;
                split_bf16(v.x,h0,l0); split_bf16(v.y,h1,l1);
                split_bf16(v.z,h2,l2); split_bf16(v.w,h3,l3);
                uint32_t off = SW(rpf[it] * 128 + qpf[it] * 8);
                *(uint2*)(nbp + P_AH + off) = pack4(h0,h1,h2,h3);
                *(uint2*)(nbp + P_AL + off) = pack4(l0,l1,l2,l3);
            }
        }
        CP_WAIT0();
        __syncthreads();
    }
    // ---- epilogue: write TRANSPOSED xftT[c][row] ----
#pragma unroll
    for (int mf = 0; mf < 4; mf++) {
        int row = row0 + wm*64 + mf*16 + (lane >> 2);
#pragma unroll
        for (int nf = 0; nf < 4; nf++) {
            int col = c0 + wn*32 + nf*8 + (lane & 3) * 2;
            g_xftT[(size_t)col       * NROWS + row]     = acc[mf][nf][0];
            g_xftT[(size_t)(col + 1) * NROWS + row]     = acc[mf][nf][1];
            g_xftT[(size_t)col       * NROWS + row + 8] = acc[mf][nf][2];
            g_xftT[(size_t)(col + 1) * NROWS + row + 8] = acc[mf][nf][3];
        }
    }
}

// ---------------------------------------------------------------------------
// MMA mode mixing. CTA = (mode m, 64-wide o slice). M=32(b), N=64(o), K=256(i).
// C_re = Xre*Wre + (-Xim)*Wim ; C_im = Xre*Wim + Xim*Wre. 3-product bf16 split.
// Warps: wg = wid>>2 (0:re, 1:im), wn = wid&3 (16-wide n slice).
// ---------------------------------------------------------------------------
#define AX_REH 0
#define AX_IMH 32768
#define AX_INH 65536
#define WX_BASE 98304
#define WX_BUF  32768
#define SMEM_MIX (WX_BASE + 2*WX_BUF)   // 160KB

__global__ void __launch_bounds__(256, 1) k_mixmma() {
    extern __shared__ char sm[];
    uint32_t sb = smem_u32(sm);
    const int tid = threadIdx.x, lane = tid & 31, wid = tid >> 5;
    const int wg = wid >> 2, wn = wid & 3;
    const int m  = blockIdx.x;
    const int o0 = blockIdx.y * 64;

    // ---- W chunk 0 via cp.async ----
    {
        const int k0 = 0;
#pragma unroll
        for (int j = 0; j < 8; j++) {
            int f = tid + j * 256;
            int p = f >> 9, r = (f >> 3) & 63, cb = f & 7;
            const __nv_bfloat16* src = (p == 0) ? gWre_h : (p == 1) ? gWre_l
                                     : (p == 2) ? gWim_h : gWim_l;
            CP16(sb + WX_BASE + p * 8192 + SW(r * 128 + cb * 16),
                 src + ((size_t)m * CH + o0 + r) * CH + k0 + cb * 8);
        }
        CP_COMMIT();
    }
    // ---- A preload: all K, 6 planes (re, im, -im) h/l ----
    {
        const float* xre = &g_xftT[(size_t)(2 * m) * NROWS];
        const float* xim = &g_xftT[(size_t)(2 * m + 1) * NROWS];
#pragma unroll
        for (int j = 0; j < 8; j++) {
            int f = tid + j * 256;           // 2048 = 32b x 64 quads
            int b = f >> 6, q = f & 63;
            int chunk = q >> 4, iq = q & 15;
            uint32_t off = chunk * 4096 + SW(b * 128 + iq * 8);
            float4 vr = *(const float4*)&xre[(size_t)b * CH + q * 4];
            float4 vi = *(const float4*)&xim[(size_t)b * CH + q * 4];
            __nv_bfloat16 h0,l0,h1,l1,h2,l2,h3,l3;
            split_bf16(vr.x,h0,l0); split_bf16(vr.y,h1,l1);
            split_bf16(vr.z,h2,l2); split_bf16(vr.w,h3,l3);
            *(uint2*)(sm + AX_REH + off)         = pack4(h0,h1,h2,h3);
            *(uint2*)(sm + AX_REH + 16384 + off) = pack4(l0,l1,l2,l3);
            split_bf16(vi.x,h0,l0); split_bf16(vi.y,h1,l1);
            split_bf16(vi.z,h2,l2); split_bf16(vi.w,h3,l3);
            *(uint2*)(sm + AX_IMH + off)         = pack4(h0,h1,h2,h3);
            *(uint2*)(sm + AX_IMH + 16384 + off) = pack4(l0,l1,l2,l3);
            split_bf16(-vi.x,h0,l0); split_bf16(-vi.y,h1,l1);
            split_bf16(-vi.z,h2,l2); split_bf16(-vi.w,h3,l3);
            *(uint2*)(sm + AX_INH + off)         = pack4(h0,h1,h2,h3);
            *(uint2*)(sm + AX_INH + 16384 + off) = pack4(l0,l1,l2,l3);
        }
    }
    CP_WAIT0();
    __syncthreads();

    uint32_t offA[2], offB;
#pragma unroll
    for (int mf = 0; mf < 2; mf++)
        offA[mf] = (mf*16 + (lane & 15)) * 128 + (lane >> 4) * 16;
    offB = (wn*16 + ((lane >> 4) << 3) + (lane & 7)) * 128 + ((lane >> 3) & 1) * 16;

    // combo plane bases: combo0 = Xre x B1, combo1 = (wg? Xim : -Xim) x B2
    const uint32_t a2base = sb + (wg ? AX_IMH : AX_INH);
    const uint32_t b1off  = wg ? 16384u : 0u;      // W_IMH : W_REH
    const uint32_t b2off  = wg ? 0u : 16384u;      // W_REH : W_IMH

    float acc[2][2][4];
#pragma unroll
    for (int i = 0; i < 2; i++)
#pragma unroll
        for (int j = 0; j < 2; j++)
#pragma unroll
            for (int q = 0; q < 4; q++) acc[i][j][q] = 0.0f;

    for (int cc = 0; cc < 4; cc++) {
        uint32_t wb = sb + WX_BASE + (cc & 1) * WX_BUF;
        if (cc < 3) {
            const int k1 = (cc + 1) * 64;
            uint32_t nwb = sb + WX_BASE + ((cc + 1) & 1) * WX_BUF;
#pragma unroll
            for (int j = 0; j < 8; j++) {
                int f = tid + j * 256;
                int p = f >> 9, r = (f >> 3) & 63, cb = f & 7;
                const __nv_bfloat16* src = (p == 0) ? gWre_h : (p == 1) ? gWre_l
                                         : (p == 2) ? gWim_h : gWim_l;
                CP16(nwb + p * 8192 + SW(r * 128 + cb * 16),
                     src + ((size_t)m * CH + o0 + r) * CH + k1 + cb * 8);
            }
            CP_COMMIT();
        }
#pragma unroll
        for (int ks = 0; ks < 4; ks++) {
#pragma unroll
            for (int combo = 0; combo < 2; combo++) {
                uint32_t ab = (combo ? a2base : (sb + AX_REH)) + cc * 4096;
                uint32_t bb = wb + (combo ? b2off : b1off);
                uint32_t Ah[2][4], Al[2][4], Bh[4], Bl[4];
#pragma unroll
                for (int mf = 0; mf < 2; mf++) {
                    LDSM4(Ah[mf], ab + SW(offA[mf] + ks * 32));
                    LDSM4(Al[mf], ab + 16384 + SW(offA[mf] + ks * 32));
                }
                LDSM4(Bh, bb + SW(offB + ks * 32));
                LDSM4(Bl, bb + 8192 + SW(offB + ks * 32));
#pragma unroll
                for (int mf = 0; mf < 2; mf++)
#pragma unroll
                    for (int nf = 0; nf < 2; nf++) {
                        MMA4(acc[mf][nf], Ah[mf], Bh[nf*2], Bh[nf*2+1]);
                        MMA4(acc[mf][nf], Al[mf], Bh[nf*2], Bh[nf*2+1]);
                        MMA4(acc[mf][nf], Ah[mf], Bl[nf*2], Bl[nf*2+1]);
                    }
            }
        }
        CP_WAIT0();
        __syncthreads();
    }

    // ---- epilogue: scale + split + store to g_oft planes ----
    const float sc = (m == 0 ? 1.0f : 2.0f) * (1.0f / (float)M_SIZE);
    const int cidx = 2 * m + wg;
#pragma unroll
    for (int mf = 0; mf < 2; mf++) {
#pragma unroll
        for (int nf = 0; nf < 2; nf++) {
#pragma unroll
            for (int h = 0; h < 2; h++) {
                int b  = mf*16 + (lane >> 2) + h * 8;
                int oo = o0 + wn*16 + nf*8 + (lane & 3) * 2;
                float v0 = acc[mf][nf][h*2]     * sc;
                float v1 = acc[mf][nf][h*2 + 1] * sc;
                __nv_bfloat16 hh, ll;
                size_t i0 = ((size_t)b * CH + oo) * NC + cidx;
                split_bf16(v0, hh, ll); g_oft_h[i0] = hh; g_oft_l[i0] = ll;
                size_t i1 = ((size_t)b * CH + oo + 1) * NC + cidx;
                split_bf16(v1, hh, ll); g_oft_h[i1] = hh; g_oft_l[i1] = ll;
            }
        }
    }
}

// ---------------------------------------------------------------------------
// Inverse DFT + LeakyReLU + residual (R4-proven).
// ---------------------------------------------------------------------------
__global__ void __launch_bounds__(256, 1) k_inv(const float* __restrict__ x,
                                                float* __restrict__ out) {
    extern __shared__ char sm[];
    uint32_t sb = smem_u32(sm);
    const int tid = threadIdx.x, lane = tid & 31, wid = tid >> 5;
    const int wm = wid & 1, wn = wid >> 1;
    const int t0   = blockIdx.x * 128;
    const int row0 = blockIdx.y * 128;

    uint32_t offA[4], offB[2];
#pragma unroll
    for (int mf = 0; mf < 4; mf++)
        offA[mf] = (wm*64 + mf*16 + (lane & 15)) * 128 + (lane >> 4) * 16;
#pragma unroll
    for (int p = 0; p < 2; p++)
        offB[p] = (wn*32 + p*16 + ((lane >> 4) << 3) + (lane & 7)) * 128
                + ((lane >> 3) & 1) * 16;

    float acc[4][4][4];
#pragma unroll
    for (int i = 0; i < 4; i++)
#pragma unroll
        for (int j = 0; j < 4; j++)
#pragma unroll
            for (int q = 0; q < 4; q++) acc[i][j][q] = 0.0f;

    {
        const int k0 = 0;
#pragma unroll
        for (int j = 0; j < 8; j++) {
            int f = tid + j * 256;
            int plane = f >> 10, r = (f >> 3) & 127, cb = f & 7;
            const __nv_bfloat16* src = (plane ? g_oft_l : g_oft_h)
                                     + (size_t)(row0 + r) * NC + k0 + cb * 8;
            CP16(sb + P_AH + plane * 16384 + SW(r * 128 + cb * 16), src);
        }
#pragma unroll
        for (int j = 0; j < 8; j++) {
            int f = tid + j * 256;
            int plane = f >> 10, r = (f >> 3) & 127, cb = f & 7;
            const __nv_bfloat16* src = (plane ? g_basis_l : g_basis_h)
                                     + (size_t)(t0 + r) * NC + k0 + cb * 8;
            CP16(sb + P_BH + plane * 16384 + SW(r * 128 + cb * 16), src);
        }
        CP_COMMIT();
        CP_WAIT0();
    }
    __syncthreads();

    const int NCHUNK = NC / 64;
    for (int cc = 0; cc < NCHUNK; cc++) {
        uint32_t bb  = sb + (cc & 1) * BUFB;
        uint32_t nbb = sb + ((cc + 1) & 1) * BUFB;
        if (cc + 1 < NCHUNK) {
            const int k1 = (cc + 1) * 64;
#pragma unroll
            for (int j = 0; j < 8; j++) {
                int f = tid + j * 256;
                int plane = f >> 10, r = (f >> 3) & 127, cb = f & 7;
                const __nv_bfloat16* src = (plane ? g_oft_l : g_oft_h)
                                         + (size_t)(row0 + r) * NC + k1 + cb * 8;
                CP16(nbb + P_AH + plane * 16384 + SW(r * 128 + cb * 16), src);
            }
#pragma unroll
            for (int j = 0; j < 8; j++) {
                int f = tid + j * 256;
                int plane = f >> 10, r = (f >> 3) & 127, cb = f & 7;
                const __nv_bfloat16* src = (plane ? g_basis_l : g_basis_h)
                                         + (size_t)(t0 + r) * NC + k1 + cb * 8;
                CP16(nbb + P_BH + plane * 16384 + SW(r * 128 + cb * 16), src);
            }
            CP_COMMIT();
        }
#pragma unroll
        for (int ks = 0; ks < 4; ks++) {
            uint32_t Af[4][4], Bh[2][4], Bo[2][4];
#pragma unroll
            for (int mf = 0; mf < 4; mf++) LDSM4(Af[mf], bb + P_AH + SW(offA[mf] + ks * 32));
#pragma unroll
            for (int p = 0; p < 2; p++)    LDSM4(Bh[p],  bb + P_BH + SW(offB[p] + ks * 32));
#pragma unroll
            for (int mf = 0; mf < 4; mf++)
#pragma unroll
                for (int nf = 0; nf < 4; nf++)
                    MMA4(acc[mf][nf], Af[mf], Bh[nf>>1][(nf&1)*2], Bh[nf>>1][(nf&1)*2+1]);
#pragma unroll
            for (int p = 0; p < 2; p++)    LDSM4(Bo[p],  bb + P_BL + SW(offB[p] + ks * 32));
#pragma unroll
            for (int mf = 0; mf < 4; mf++)
#pragma unroll
                for (int nf = 0; nf < 4; nf++)
                    MMA4(acc[mf][nf], Af[mf], Bo[nf>>1][(nf&1)*2], Bo[nf>>1][(nf&1)*2+1]);
#pragma unroll
            for (int mf = 0; mf < 4; mf++) LDSM4(Af[mf], bb + P_AL + SW(offA[mf] + ks * 32));
#pragma unroll
            for (int mf = 0; mf < 4; mf++)
#pragma unroll
                for (int nf = 0; nf < 4; nf++)
                    MMA4(acc[mf][nf], Af[mf], Bh[nf>>1][(nf&1)*2], Bh[nf>>1][(nf&1)*2+1]);
        }
        CP_WAIT0();
        __syncthreads();
    }
#pragma unroll
    for (int mf = 0; mf < 4; mf++) {
        int row = row0 + wm*64 + mf*16 + (lane >> 2);
#pragma unroll
        for (int nf = 0; nf < 4; nf++) {
            int tc = t0 + wn*32 + nf*8 + (lane & 3) * 2;
#pragma unroll
            for (int h = 0; h < 2; h++) {
                size_t base = (size_t)(row + h * 8) * M_SIZE + tc;
                float2 xv = *(const float2*)&x[base];
                float v0 = acc[mf][nf][h*2], v1 = acc[mf][nf][h*2+1];
                float2 rv;
                rv.x = xv.x + (v0 >= 0.f ? v0 : 0.2f * v0);
                rv.y = xv.y + (v1 >= 0.f ? v1 : 0.2f * v1);
                *(float2*)&out[base] = rv;
            }
        }
    }
}

// ---------------------------------------------------------------------------
extern "C" void kernel_launch(void* const* d_in, const int* in_sizes, int n_in,
                              void* d_out, int out_size) {
    (void)in_sizes; (void)n_in; (void)out_size;
    const float*  x  = (const float*)d_in[0];
    const float2* w2 = (const float2*)d_in[1];
    float* out = (float*)d_out;

    cudaFuncSetAttribute(k_fwd,    cudaFuncAttributeMaxDynamicSharedMemorySize, SMEM_GEMM);
    cudaFuncSetAttribute(k_inv,    cudaFuncAttributeMaxDynamicSharedMemorySize, SMEM_GEMM);
    cudaFuncSetAttribute(k_mixmma, cudaFuncAttributeMaxDynamicSharedMemorySize, SMEM_MIX);

    k_basis_a<<<(M_SIZE * NMODES) / 256, 256>>>();
    k_basis_b<<<(M_SIZE * NMODES) / 256, 256>>>();
    k_wtransp<<<dim3(CH / 64, NMODES / 32, CH), 256>>>(w2);
    k_fwd<<<dim3(NROWS / 128, NC / 128), 256, SMEM_GEMM>>>(x);
    k_mixmma<<<dim3(NMODES, CH / 64), 256, SMEM_MIX>>>();
    k_inv<<<dim3(M_SIZE / 128, NROWS / 128), 256, SMEM_GEMM>>>(x, out);
}